// round 10
// baseline (speedup 1.0000x reference)
#include <cuda_runtime.h>
#include <cuda_fp16.h>
#include <cstdint>

#define TOKENS 8192
#define OUT_F  4096
#define IN_F   4096

// Scratch (allocation-guard-safe __device__ globals): 64 MB each.
__device__ __half g_W[(size_t)OUT_F * IN_F];
__device__ __half g_X[(size_t)TOKENS * IN_F];

// ---------------------------------------------------------------------------
// Fused prep: blocks [0, 16384) convert x f32->fp16; blocks [16384, 24576)
// dequant packed nibbles -> fp16 W. Both memory-bound; one launch.
// ---------------------------------------------------------------------------
#define X_BLOCKS 16384           // 8192*4096/8 elems-per-thread /256
#define W_BLOCKS 8192            // (OUT_F*IN_F/2)/4 bytes-per-thread /256

__global__ void prep_kernel(const float* __restrict__ xf,
                            const int* __restrict__ qw,
                            const int* __restrict__ absmax1,
                            const float* __restrict__ code1,
                            const float* __restrict__ offset1,
                            const float* __restrict__ absmax2,
                            const float* __restrict__ code2) {
    if (blockIdx.x < X_BLOCKS) {
        size_t t = (size_t)blockIdx.x * blockDim.x + threadIdx.x;
        float4 f0 = ((const float4*)xf)[2 * t];
        float4 f1 = ((const float4*)xf)[2 * t + 1];
        __half2 h[4];
        h[0] = __floats2half2_rn(f0.x, f0.y);
        h[1] = __floats2half2_rn(f0.z, f0.w);
        h[2] = __floats2half2_rn(f1.x, f1.y);
        h[3] = __floats2half2_rn(f1.z, f1.w);
        ((int4*)g_X)[t] = *(int4*)h;
    } else {
        int t = (blockIdx.x - X_BLOCKS) * blockDim.x + threadIdx.x;
        int p0 = t * 4;                      // first packed byte index
        int4 q4 = ((const int4*)qw)[t];
        int blk1 = p0 >> 5;                  // 32 packed bytes per primary blk
        int blk2 = p0 >> 7;                  // 128 packed bytes per secondary
        float scale = ((float)absmax1[blk1] / code1[blk1]) *
                      (absmax2[blk2] / code2[blk2]);
        float off = offset1[blk1];
        int b[4] = {q4.x, q4.y, q4.z, q4.w};
        __half2 o[4];
#pragma unroll
        for (int j = 0; j < 4; j++) {
            float lo = (float)(b[j] & 15);
            float hi = (float)((b[j] >> 4) & 15);
            o[j] = __floats2half2_rn((lo - off) * scale, (hi - off) * scale);
        }
        ((int4*)g_W)[t] = *(int4*)o;         // elements [8t, 8t+8)
    }
}

// ---------------------------------------------------------------------------
// GEMM: out[8192,4096](f32, fp16-rounded) = X[M,K](f16) * W[N,K](f16)^T
// mma.sync m16n8k16 f32-accum. BM=128 BN=256 BK=64, 4-stage cp.async,
// 256 threads (8 warps, 2x4 warp grid, warp tile 64x64), 1 sync/iter.
// ---------------------------------------------------------------------------
#define BM 128
#define BN 256
#define BK 64
#define STAGES 4
#define KITERS (IN_F / BK)                 // 64
#define LDS_ (BK + 8)                      // 72 halves = 144B row stride
#define A_SM (BM * LDS_)                   // halves
#define B_SM (BN * LDS_)
#define STG_SM (A_SM + B_SM)               // 27648 halves per stage
#define GEMM_SMEM (STAGES * STG_SM * 2)    // 221184 bytes

__device__ __forceinline__ uint32_t smem_u32(const void* p) {
    return (uint32_t)__cvta_generic_to_shared(p);
}
__device__ __forceinline__ void cp_async16(uint32_t s, const void* g) {
    asm volatile("cp.async.cg.shared.global [%0], [%1], 16;\n" :: "r"(s), "l"(g));
}
__device__ __forceinline__ void cp_commit() {
    asm volatile("cp.async.commit_group;\n");
}
template<int N_> __device__ __forceinline__ void cp_wait() {
    asm volatile("cp.async.wait_group %0;\n" :: "n"(N_));
}
__device__ __forceinline__ void ldm_x4(uint32_t& r0, uint32_t& r1,
                                       uint32_t& r2, uint32_t& r3, uint32_t a) {
    asm volatile("ldmatrix.sync.aligned.m8n8.x4.shared.b16 {%0,%1,%2,%3}, [%4];"
                 : "=r"(r0), "=r"(r1), "=r"(r2), "=r"(r3) : "r"(a));
}

__global__ void __launch_bounds__(256, 1)
gemm_kernel(float* __restrict__ O) {
    extern __shared__ __align__(16) __half smem[];

    const int tid  = threadIdx.x;
    const int warp = tid >> 5;
    const int lane = tid & 31;
    const int wm   = warp & 1;    // 2 warps over M: 64 rows each
    const int wn   = warp >> 1;   // 4 warps over N: 64 cols each
    const int bm   = blockIdx.y * BM;
    const int bn   = blockIdx.x * BN;

    // Per stage: A = 1024 16B chunks, B = 2048 chunks; 256 threads x 12.
    // chunk c: row = c>>3, col = (c&7)*8 halves.
#define LOAD_TILES(stage, kt)                                                  \
    do {                                                                       \
        const int k0 = (kt) * BK;                                              \
        __half* As = smem + (size_t)(stage) * STG_SM;                          \
        __half* Bs = As + A_SM;                                                \
        _Pragma("unroll")                                                      \
        for (int i = 0; i < 4; i++) {                                          \
            int c = tid + i * 256;                                             \
            int r = c >> 3, cc = (c & 7) * 8;                                  \
            cp_async16(smem_u32(As + r * LDS_ + cc),                           \
                       g_X + (size_t)(bm + r) * IN_F + k0 + cc);               \
        }                                                                      \
        _Pragma("unroll")                                                      \
        for (int i = 0; i < 8; i++) {                                          \
            int c = tid + i * 256;                                             \
            int r = c >> 3, cc = (c & 7) * 8;                                  \
            cp_async16(smem_u32(Bs + r * LDS_ + cc),                           \
                       g_W + (size_t)(bn + r) * IN_F + k0 + cc);               \
        }                                                                      \
    } while (0)

    float acc[4][8][4] = {};

    LOAD_TILES(0, 0); cp_commit();
    LOAD_TILES(1, 1); cp_commit();
    LOAD_TILES(2, 2); cp_commit();

    for (int kt = 0; kt < KITERS; kt++) {
        cp_wait<2>();
        __syncthreads();
        if (kt + 3 < KITERS) LOAD_TILES((kt + 3) % STAGES, kt + 3);
        cp_commit();

        const __half* As = smem + (size_t)(kt % STAGES) * STG_SM;
        const __half* Bs = As + A_SM;

#pragma unroll
        for (int kk = 0; kk < BK; kk += 16) {
            uint32_t a[4][4];
#pragma unroll
            for (int im = 0; im < 4; im++) {
                int row = wm * 64 + im * 16 + (lane & 15);
                int col = kk + (lane >> 4) * 8;
                ldm_x4(a[im][0], a[im][1], a[im][2], a[im][3],
                       smem_u32(As + row * LDS_ + col));
            }
            uint32_t b[8][2];
#pragma unroll
            for (int ib = 0; ib < 4; ib++) {
                int row = wn * 64 + ib * 16 + (lane & 7) + ((lane >> 4) << 3);
                int col = kk + ((lane >> 3) & 1) * 8;
                uint32_t q0, q1, q2, q3;
                ldm_x4(q0, q1, q2, q3, smem_u32(Bs + row * LDS_ + col));
                b[ib * 2][0] = q0;     b[ib * 2][1] = q1;
                b[ib * 2 + 1][0] = q2; b[ib * 2 + 1][1] = q3;
            }
#pragma unroll
            for (int im = 0; im < 4; im++)
#pragma unroll
                for (int in = 0; in < 8; in++) {
                    asm volatile(
                        "mma.sync.aligned.m16n8k16.row.col.f32.f16.f16.f32 "
                        "{%0,%1,%2,%3},{%4,%5,%6,%7},{%8,%9},{%0,%1,%2,%3};"
                        : "+f"(acc[im][in][0]), "+f"(acc[im][in][1]),
                          "+f"(acc[im][in][2]), "+f"(acc[im][in][3])
                        : "r"(a[im][0]), "r"(a[im][1]),
                          "r"(a[im][2]), "r"(a[im][3]),
                          "r"(b[in][0]), "r"(b[in][1]));
                }
        }
    }

    // Epilogue: round through fp16 (reference dequant-matmul is fp16), store f32.
    const int gid  = lane >> 2;
    const int tid4 = lane & 3;
#pragma unroll
    for (int im = 0; im < 4; im++)
#pragma unroll
        for (int in = 0; in < 8; in++) {
            int n = bn + wn * 64 + in * 8 + tid4 * 2;
#pragma unroll
            for (int r = 0; r < 2; r++) {
                int m = bm + wm * 64 + im * 16 + gid + r * 8;
                float2 v;
                v.x = __half2float(__float2half_rn(acc[im][in][r * 2]));
                v.y = __half2float(__float2half_rn(acc[im][in][r * 2 + 1]));
                *(float2*)(O + (size_t)m * OUT_F + n) = v;
            }
        }
#undef LOAD_TILES
}

// ---------------------------------------------------------------------------
// Inputs (metadata order): x f32, quantized_weight i32, quant_absmax i32,
// quant_code f32, quant_offset f32, state2_absmax f32, state2_code f32.
// Output: float32 [TOKENS, OUT_F].
// ---------------------------------------------------------------------------
extern "C" void kernel_launch(void* const* d_in, const int* in_sizes, int n_in,
                              void* d_out, int out_size) {
    const float* x   = (const float*)d_in[0];
    const int*   qw  = (const int*)d_in[1];
    const int*   am1 = (const int*)d_in[2];
    const float* cd1 = (const float*)d_in[3];
    const float* of1 = (const float*)d_in[4];
    const float* am2 = (const float*)d_in[5];
    const float* cd2 = (const float*)d_in[6];
    float* out = (float*)d_out;

    prep_kernel<<<X_BLOCKS + W_BLOCKS, 256>>>(x, qw, am1, cd1, of1, am2, cd2);

    cudaFuncSetAttribute(gemm_kernel,
                         cudaFuncAttributeMaxDynamicSharedMemorySize, GEMM_SMEM);

    dim3 grid(OUT_F / BN, TOKENS / BM);
    gemm_kernel<<<grid, 256, GEMM_SMEM>>>(out);
}

// round 11
// speedup vs baseline: 1.1093x; 1.1093x over previous
#include <cuda_runtime.h>
#include <cuda_fp16.h>
#include <cstdint>

#define TOKENS 8192
#define OUT_F  4096
#define IN_F   4096

// Scratch (allocation-guard-safe __device__ globals): 64 MB each.
__device__ __half g_W[(size_t)OUT_F * IN_F];
__device__ __half g_X[(size_t)TOKENS * IN_F];

// ---------------------------------------------------------------------------
// Fused prep: blocks [0, 16384) convert x f32->fp16; blocks [16384, 24576)
// dequant packed nibbles -> fp16 W. Both memory-bound; one launch.
// ---------------------------------------------------------------------------
#define X_BLOCKS 16384           // 8192*4096/8 elems-per-thread /256
#define W_BLOCKS 8192            // (OUT_F*IN_F/2)/4 bytes-per-thread /256

__global__ void prep_kernel(const float* __restrict__ xf,
                            const int* __restrict__ qw,
                            const int* __restrict__ absmax1,
                            const float* __restrict__ code1,
                            const float* __restrict__ offset1,
                            const float* __restrict__ absmax2,
                            const float* __restrict__ code2) {
    if (blockIdx.x < X_BLOCKS) {
        size_t t = (size_t)blockIdx.x * blockDim.x + threadIdx.x;
        float4 f0 = ((const float4*)xf)[2 * t];
        float4 f1 = ((const float4*)xf)[2 * t + 1];
        __half2 h[4];
        h[0] = __floats2half2_rn(f0.x, f0.y);
        h[1] = __floats2half2_rn(f0.z, f0.w);
        h[2] = __floats2half2_rn(f1.x, f1.y);
        h[3] = __floats2half2_rn(f1.z, f1.w);
        ((int4*)g_X)[t] = *(int4*)h;
    } else {
        int t = (blockIdx.x - X_BLOCKS) * blockDim.x + threadIdx.x;
        int p0 = t * 4;                      // first packed byte index
        int4 q4 = ((const int4*)qw)[t];
        int blk1 = p0 >> 5;                  // 32 packed bytes per primary blk
        int blk2 = p0 >> 7;                  // 128 packed bytes per secondary
        float scale = ((float)absmax1[blk1] / code1[blk1]) *
                      (absmax2[blk2] / code2[blk2]);
        float off = offset1[blk1];
        int b[4] = {q4.x, q4.y, q4.z, q4.w};
        __half2 o[4];
#pragma unroll
        for (int j = 0; j < 4; j++) {
            float lo = (float)(b[j] & 15);
            float hi = (float)((b[j] >> 4) & 15);
            o[j] = __floats2half2_rn((lo - off) * scale, (hi - off) * scale);
        }
        ((int4*)g_W)[t] = *(int4*)o;         // elements [8t, 8t+8)
    }
}

// ---------------------------------------------------------------------------
// GEMM: out[8192,4096](f32, fp16-rounded) = X[M,K](f16) * W[N,K](f16)^T
// mma.sync m16n8k16 f32-accum. BM=128 BN=128 BK=64, 3-stage cp.async.
// 128 threads (4 warps, 2x2 grid, warp tile 64x64), 2 CTAs/SM,
// fragment double-buffering across kk (ldm for kk+16 overlaps MMA for kk).
// ---------------------------------------------------------------------------
#define BM 128
#define BN 128
#define BK 64
#define STAGES 3
#define KITERS (IN_F / BK)                 // 64
#define LDS_ (BK + 8)                      // 72 halves = 144B row stride
#define A_SM (BM * LDS_)                   // halves
#define B_SM (BN * LDS_)
#define STG_SM (A_SM + B_SM)               // 18432 halves per stage
#define GEMM_SMEM (STAGES * STG_SM * 2)    // 110592 bytes per CTA

__device__ __forceinline__ uint32_t smem_u32(const void* p) {
    return (uint32_t)__cvta_generic_to_shared(p);
}
__device__ __forceinline__ void cp_async16(uint32_t s, const void* g) {
    asm volatile("cp.async.cg.shared.global [%0], [%1], 16;\n" :: "r"(s), "l"(g));
}
__device__ __forceinline__ void cp_commit() {
    asm volatile("cp.async.commit_group;\n");
}
template<int N_> __device__ __forceinline__ void cp_wait() {
    asm volatile("cp.async.wait_group %0;\n" :: "n"(N_));
}
__device__ __forceinline__ void ldm_x4(uint32_t& r0, uint32_t& r1,
                                       uint32_t& r2, uint32_t& r3, uint32_t a) {
    asm volatile("ldmatrix.sync.aligned.m8n8.x4.shared.b16 {%0,%1,%2,%3}, [%4];"
                 : "=r"(r0), "=r"(r1), "=r"(r2), "=r"(r3) : "r"(a));
}

__global__ void __launch_bounds__(128, 2)
gemm_kernel(float* __restrict__ O) {
    extern __shared__ __align__(16) __half smem[];

    const int tid  = threadIdx.x;
    const int warp = tid >> 5;
    const int lane = tid & 31;
    const int wm   = warp & 1;    // 2 warps over M: 64 rows each
    const int wn   = warp >> 1;   // 2 warps over N: 64 cols each
    const int bm   = blockIdx.y * BM;
    const int bn   = blockIdx.x * BN;

    // Per stage: A = 1024 16B chunks, B = 1024; 128 threads x 16.
#define LOAD_TILES(stage, kt)                                                  \
    do {                                                                       \
        const int k0 = (kt) * BK;                                              \
        __half* As_ = smem + (size_t)(stage) * STG_SM;                         \
        __half* Bs_ = As_ + A_SM;                                              \
        _Pragma("unroll")                                                      \
        for (int i = 0; i < 8; i++) {                                          \
            int c = tid + i * 128;                                             \
            int r = c >> 3, cc = (c & 7) * 8;                                  \
            cp_async16(smem_u32(As_ + r * LDS_ + cc),                          \
                       g_X + (size_t)(bm + r) * IN_F + k0 + cc);               \
        }                                                                      \
        _Pragma("unroll")                                                      \
        for (int i = 0; i < 8; i++) {                                          \
            int c = tid + i * 128;                                             \
            int r = c >> 3, cc = (c & 7) * 8;                                  \
            cp_async16(smem_u32(Bs_ + r * LDS_ + cc),                          \
                       g_W + (size_t)(bn + r) * IN_F + k0 + cc);               \
        }                                                                      \
    } while (0)

    // Load all fragments for one kk (16-wide K slice) into buffer `buf`.
#define LDM_FRAGS(buf, As_, Bs_, kk)                                           \
    do {                                                                       \
        _Pragma("unroll")                                                      \
        for (int im = 0; im < 4; im++) {                                       \
            int row = wm * 64 + im * 16 + (lane & 15);                         \
            int col = (kk) + (lane >> 4) * 8;                                  \
            ldm_x4(afr[buf][im][0], afr[buf][im][1],                           \
                   afr[buf][im][2], afr[buf][im][3],                           \
                   smem_u32((As_) + row * LDS_ + col));                        \
        }                                                                      \
        _Pragma("unroll")                                                      \
        for (int ib = 0; ib < 4; ib++) {                                       \
            int row = wn * 64 + ib * 16 + (lane & 7) + ((lane >> 4) << 3);     \
            int col = (kk) + ((lane >> 3) & 1) * 8;                            \
            ldm_x4(bfr[buf][ib * 2][0], bfr[buf][ib * 2][1],                   \
                   bfr[buf][ib * 2 + 1][0], bfr[buf][ib * 2 + 1][1],           \
                   smem_u32((Bs_) + row * LDS_ + col));                        \
        }                                                                      \
    } while (0)

    float acc[4][8][4] = {};
    uint32_t afr[2][4][4];
    uint32_t bfr[2][8][2];

    LOAD_TILES(0, 0); cp_commit();
    LOAD_TILES(1, 1); cp_commit();

    for (int kt = 0; kt < KITERS; kt++) {
        cp_wait<1>();
        __syncthreads();

        const __half* As = smem + (size_t)(kt % STAGES) * STG_SM;
        const __half* Bs = As + A_SM;

        LDM_FRAGS(0, As, Bs, 0);               // first slice's frags
        if (kt + 2 < KITERS) LOAD_TILES((kt + 2) % STAGES, kt + 2);
        cp_commit();

#pragma unroll
        for (int s16 = 0; s16 < 4; s16++) {
            const int cur = s16 & 1;
            if (s16 < 3) LDM_FRAGS(cur ^ 1, As, Bs, (s16 + 1) * 16);
#pragma unroll
            for (int im = 0; im < 4; im++)
#pragma unroll
                for (int in = 0; in < 8; in++) {
                    asm volatile(
                        "mma.sync.aligned.m16n8k16.row.col.f32.f16.f16.f32 "
                        "{%0,%1,%2,%3},{%4,%5,%6,%7},{%8,%9},{%0,%1,%2,%3};"
                        : "+f"(acc[im][in][0]), "+f"(acc[im][in][1]),
                          "+f"(acc[im][in][2]), "+f"(acc[im][in][3])
                        : "r"(afr[cur][im][0]), "r"(afr[cur][im][1]),
                          "r"(afr[cur][im][2]), "r"(afr[cur][im][3]),
                          "r"(bfr[cur][in][0]), "r"(bfr[cur][in][1]));
                }
        }
    }

    // Epilogue: round through fp16 (reference dequant-matmul is fp16), store f32.
    const int gid  = lane >> 2;
    const int tid4 = lane & 3;
#pragma unroll
    for (int im = 0; im < 4; im++)
#pragma unroll
        for (int in = 0; in < 8; in++) {
            int n = bn + wn * 64 + in * 8 + tid4 * 2;
#pragma unroll
            for (int r = 0; r < 2; r++) {
                int m = bm + wm * 64 + im * 16 + gid + r * 8;
                float2 v;
                v.x = __half2float(__float2half_rn(acc[im][in][r * 2]));
                v.y = __half2float(__float2half_rn(acc[im][in][r * 2 + 1]));
                *(float2*)(O + (size_t)m * OUT_F + n) = v;
            }
        }
#undef LOAD_TILES
#undef LDM_FRAGS
}

// ---------------------------------------------------------------------------
// Inputs (metadata order): x f32, quantized_weight i32, quant_absmax i32,
// quant_code f32, quant_offset f32, state2_absmax f32, state2_code f32.
// Output: float32 [TOKENS, OUT_F].
// ---------------------------------------------------------------------------
extern "C" void kernel_launch(void* const* d_in, const int* in_sizes, int n_in,
                              void* d_out, int out_size) {
    const float* x   = (const float*)d_in[0];
    const int*   qw  = (const int*)d_in[1];
    const int*   am1 = (const int*)d_in[2];
    const float* cd1 = (const float*)d_in[3];
    const float* of1 = (const float*)d_in[4];
    const float* am2 = (const float*)d_in[5];
    const float* cd2 = (const float*)d_in[6];
    float* out = (float*)d_out;

    prep_kernel<<<X_BLOCKS + W_BLOCKS, 256>>>(x, qw, am1, cd1, of1, am2, cd2);

    cudaFuncSetAttribute(gemm_kernel,
                         cudaFuncAttributeMaxDynamicSharedMemorySize, GEMM_SMEM);

    dim3 grid(OUT_F / BN, TOKENS / BM);
    gemm_kernel<<<grid, 128, GEMM_SMEM>>>(out);
}

// round 14
// speedup vs baseline: 1.2314x; 1.1101x over previous
#include <cuda_runtime.h>
#include <cuda_fp16.h>
#include <cstdint>

#define TOKENS 8192
#define OUT_F  4096
#define IN_F   4096

// Scratch (allocation-guard-safe __device__ globals): 64 MB each.
__device__ __half g_W[(size_t)OUT_F * IN_F];
__device__ __half g_X[(size_t)TOKENS * IN_F];

// ---------------------------------------------------------------------------
// Fused prep: blocks [0, 16384) convert x f32->fp16; blocks [16384, 24576)
// dequant packed nibbles -> fp16 W. Both memory-bound; one launch.
// ---------------------------------------------------------------------------
#define X_BLOCKS 16384           // 8192*4096/8 elems-per-thread /256
#define W_BLOCKS 8192            // (OUT_F*IN_F/2)/4 bytes-per-thread /256

__global__ void prep_kernel(const float* __restrict__ xf,
                            const int* __restrict__ qw,
                            const int* __restrict__ absmax1,
                            const float* __restrict__ code1,
                            const float* __restrict__ offset1,
                            const float* __restrict__ absmax2,
                            const float* __restrict__ code2) {
    if (blockIdx.x < X_BLOCKS) {
        size_t t = (size_t)blockIdx.x * blockDim.x + threadIdx.x;
        float4 f0 = ((const float4*)xf)[2 * t];
        float4 f1 = ((const float4*)xf)[2 * t + 1];
        __half2 h[4];
        h[0] = __floats2half2_rn(f0.x, f0.y);
        h[1] = __floats2half2_rn(f0.z, f0.w);
        h[2] = __floats2half2_rn(f1.x, f1.y);
        h[3] = __floats2half2_rn(f1.z, f1.w);
        ((int4*)g_X)[t] = *(int4*)h;
    } else {
        int t = (blockIdx.x - X_BLOCKS) * blockDim.x + threadIdx.x;
        int p0 = t * 4;                      // first packed byte index
        int4 q4 = ((const int4*)qw)[t];
        int blk1 = p0 >> 5;                  // 32 packed bytes per primary blk
        int blk2 = p0 >> 7;                  // 128 packed bytes per secondary
        float scale = ((float)absmax1[blk1] / code1[blk1]) *
                      (absmax2[blk2] / code2[blk2]);
        float off = offset1[blk1];
        int b[4] = {q4.x, q4.y, q4.z, q4.w};
        __half2 o[4];
#pragma unroll
        for (int j = 0; j < 4; j++) {
            float lo = (float)(b[j] & 15);
            float hi = (float)((b[j] >> 4) & 15);
            o[j] = __floats2half2_rn((lo - off) * scale, (hi - off) * scale);
        }
        ((int4*)g_W)[t] = *(int4*)o;         // elements [8t, 8t+8)
    }
}

// ---------------------------------------------------------------------------
// GEMM: out[8192,4096](f32, fp16-rounded) = X[M,K](f16) * W[N,K](f16)^T
// mma.sync m16n8k16 f32-accum. BM=128 BN=128 BK=64, 3-stage cp.async.
// 128 threads (4 warps, 2x2 grid, warp tile 64x64), 2 CTAs/SM.
// Fragment pipeline crosses the iteration boundary: slice-3 MMAs run
// post-barrier on pre-loaded frags while next-iter slice-0 frags prefetch.
// Buffers ping-pong: slice0->buf0, slice1->buf1, slice2->buf0, slice3->buf1.
// ---------------------------------------------------------------------------
#define BM 128
#define BN 128
#define BK 64
#define STAGES 3
#define KITERS (IN_F / BK)                 // 64
#define LDS_ (BK + 8)                      // 72 halves = 144B row stride
#define A_SM (BM * LDS_)                   // halves
#define B_SM (BN * LDS_)
#define STG_SM (A_SM + B_SM)               // 18432 halves per stage
#define GEMM_SMEM (STAGES * STG_SM * 2)    // 110592 bytes per CTA

__device__ __forceinline__ uint32_t smem_u32(const void* p) {
    return (uint32_t)__cvta_generic_to_shared(p);
}
__device__ __forceinline__ void cp_async16(uint32_t s, const void* g) {
    asm volatile("cp.async.cg.shared.global [%0], [%1], 16;\n" :: "r"(s), "l"(g));
}
__device__ __forceinline__ void cp_commit() {
    asm volatile("cp.async.commit_group;\n");
}
template<int N_> __device__ __forceinline__ void cp_wait() {
    asm volatile("cp.async.wait_group %0;\n" :: "n"(N_));
}
__device__ __forceinline__ void cp_wait_all() {
    asm volatile("cp.async.wait_all;\n");
}
__device__ __forceinline__ void ldm_x4(uint32_t& r0, uint32_t& r1,
                                       uint32_t& r2, uint32_t& r3, uint32_t a) {
    asm volatile("ldmatrix.sync.aligned.m8n8.x4.shared.b16 {%0,%1,%2,%3}, [%4];"
                 : "=r"(r0), "=r"(r1), "=r"(r2), "=r"(r3) : "r"(a));
}

__global__ void __launch_bounds__(128, 2)
gemm_kernel(float* __restrict__ O) {
    extern __shared__ __align__(16) __half smem[];

    const int tid  = threadIdx.x;
    const int warp = tid >> 5;
    const int lane = tid & 31;
    const int wm   = warp & 1;    // 2 warps over M: 64 rows each
    const int wn   = warp >> 1;   // 2 warps over N: 64 cols each
    const int bm   = blockIdx.y * BM;
    const int bn   = blockIdx.x * BN;

    // Per stage: A = 1024 16B chunks, B = 1024; 128 threads x 16.
#define LOAD_TILES(stage, kt)                                                  \
    do {                                                                       \
        const int k0 = (kt) * BK;                                              \
        __half* As_ = smem + (size_t)(stage) * STG_SM;                         \
        __half* Bs_ = As_ + A_SM;                                              \
        _Pragma("unroll")                                                      \
        for (int i = 0; i < 8; i++) {                                          \
            int c = tid + i * 128;                                             \
            int r = c >> 3, cc = (c & 7) * 8;                                  \
            cp_async16(smem_u32(As_ + r * LDS_ + cc),                          \
                       g_X + (size_t)(bm + r) * IN_F + k0 + cc);               \
        }                                                                      \
        _Pragma("unroll")                                                      \
        for (int i = 0; i < 8; i++) {                                          \
            int c = tid + i * 128;                                             \
            int r = c >> 3, cc = (c & 7) * 8;                                  \
            cp_async16(smem_u32(Bs_ + r * LDS_ + cc),                          \
                       g_W + (size_t)(bn + r) * IN_F + k0 + cc);               \
        }                                                                      \
    } while (0)

    // Load all fragments for one 16-wide K slice into buffer `buf`.
#define LDM_FRAGS(buf, As_, Bs_, kk)                                           \
    do {                                                                       \
        _Pragma("unroll")                                                      \
        for (int im = 0; im < 4; im++) {                                       \
            int row = wm * 64 + im * 16 + (lane & 15);                         \
            int col = (kk) + (lane >> 4) * 8;                                  \
            ldm_x4(afr[buf][im][0], afr[buf][im][1],                           \
                   afr[buf][im][2], afr[buf][im][3],                           \
                   smem_u32((As_) + row * LDS_ + col));                        \
        }                                                                      \
        _Pragma("unroll")                                                      \
        for (int ib = 0; ib < 4; ib++) {                                       \
            int row = wn * 64 + ib * 16 + (lane & 7) + ((lane >> 4) << 3);     \
            int col = (kk) + ((lane >> 3) & 1) * 8;                            \
            ldm_x4(bfr[buf][ib * 2][0], bfr[buf][ib * 2][1],                   \
                   bfr[buf][ib * 2 + 1][0], bfr[buf][ib * 2 + 1][1],           \
                   smem_u32((Bs_) + row * LDS_ + col));                        \
        }                                                                      \
    } while (0)

#define MMA_SLICE(buf)                                                         \
    do {                                                                       \
        _Pragma("unroll")                                                      \
        for (int im = 0; im < 4; im++)                                         \
            _Pragma("unroll")                                                  \
            for (int in = 0; in < 8; in++) {                                   \
                asm volatile(                                                  \
                    "mma.sync.aligned.m16n8k16.row.col.f32.f16.f16.f32 "       \
                    "{%0,%1,%2,%3},{%4,%5,%6,%7},{%8,%9},{%0,%1,%2,%3};"       \
                    : "+f"(acc[im][in][0]), "+f"(acc[im][in][1]),              \
                      "+f"(acc[im][in][2]), "+f"(acc[im][in][3])               \
                    : "r"(afr[buf][im][0]), "r"(afr[buf][im][1]),              \
                      "r"(afr[buf][im][2]), "r"(afr[buf][im][3]),              \
                      "r"(bfr[buf][in][0]), "r"(bfr[buf][in][1]));             \
            }                                                                  \
    } while (0)

    float acc[4][8][4] = {};
    uint32_t afr[2][4][4];
    uint32_t bfr[2][8][2];

    LOAD_TILES(0, 0); cp_commit();
    LOAD_TILES(1, 1); cp_commit();
    cp_wait<1>();                     // stage 0 resident
    __syncthreads();
    {   // initial slice-0 fragments (iter 0) -> buf0
        const __half* As = smem;
        const __half* Bs = As + A_SM;
        LDM_FRAGS(0, As, Bs, 0);
    }

    for (int kt = 0; kt < KITERS; kt++) {
        const __half* As = smem + (size_t)(kt % STAGES) * STG_SM;
        const __half* Bs = As + A_SM;

        LDM_FRAGS(1, As, Bs, 16); MMA_SLICE(0);   // slice 0 (buf0)
        LDM_FRAGS(0, As, Bs, 32); MMA_SLICE(1);   // slice 1 (buf1)
        LDM_FRAGS(1, As, Bs, 48); MMA_SLICE(0);   // slice 2 (buf0)

        // Iteration boundary: stage kt+1 must be fully resident for the
        // cross-iter prefetch below (issued 1 full iteration ago).
        cp_wait_all();
        __syncthreads();
        if (kt + 2 < KITERS) LOAD_TILES((kt + 2) % STAGES, kt + 2);
        cp_commit();

        // slice 3: MMAs on pre-loaded buf1; prefetch next iter's slice 0
        // into buf0 from stage kt+1 in parallel (no dependency).
        if (kt + 1 < KITERS) {
            const __half* An = smem + (size_t)((kt + 1) % STAGES) * STG_SM;
            const __half* Bn = An + A_SM;
            LDM_FRAGS(0, An, Bn, 0);
        }
        MMA_SLICE(1);                             // slice 3 (buf1)
    }

    // Epilogue: round through fp16 (reference dequant-matmul is fp16), store f32.
    const int gid  = lane >> 2;
    const int tid4 = lane & 3;
#pragma unroll
    for (int im = 0; im < 4; im++)
#pragma unroll
        for (int in = 0; in < 8; in++) {
            int n = bn + wn * 64 + in * 8 + tid4 * 2;
#pragma unroll
            for (int r = 0; r < 2; r++) {
                int m = bm + wm * 64 + im * 16 + gid + r * 8;
                float2 v;
                v.x = __half2float(__float2half_rn(acc[im][in][r * 2]));
                v.y = __half2float(__float2half_rn(acc[im][in][r * 2 + 1]));
                *(float2*)(O + (size_t)m * OUT_F + n) = v;
            }
        }
#undef LOAD_TILES
#undef LDM_FRAGS
#undef MMA_SLICE
}

// ---------------------------------------------------------------------------
// Inputs (metadata order): x f32, quantized_weight i32, quant_absmax i32,
// quant_code f32, quant_offset f32, state2_absmax f32, state2_code f32.
// Output: float32 [TOKENS, OUT_F].
// ---------------------------------------------------------------------------
extern "C" void kernel_launch(void* const* d_in, const int* in_sizes, int n_in,
                              void* d_out, int out_size) {
    const float* x   = (const float*)d_in[0];
    const int*   qw  = (const int*)d_in[1];
    const int*   am1 = (const int*)d_in[2];
    const float* cd1 = (const float*)d_in[3];
    const float* of1 = (const float*)d_in[4];
    const float* am2 = (const float*)d_in[5];
    const float* cd2 = (const float*)d_in[6];
    float* out = (float*)d_out;

    prep_kernel<<<X_BLOCKS + W_BLOCKS, 256>>>(x, qw, am1, cd1, of1, am2, cd2);

    cudaFuncSetAttribute(gemm_kernel,
                         cudaFuncAttributeMaxDynamicSharedMemorySize, GEMM_SMEM);

    dim3 grid(OUT_F / BN, TOKENS / BM);
    gemm_kernel<<<grid, 128, GEMM_SMEM>>>(out);
}

// round 15
// speedup vs baseline: 1.2995x; 1.0553x over previous
#include <cuda_runtime.h>
#include <cuda_fp16.h>
#include <cstdint>

#define TOKENS 8192
#define OUT_F  4096
#define IN_F   4096

// Scratch (allocation-guard-safe __device__ globals): 64 MB each.
__device__ __half g_W[(size_t)OUT_F * IN_F];
__device__ __half g_X[(size_t)TOKENS * IN_F];

// ---------------------------------------------------------------------------
// Fused prep: blocks [0, 16384) convert x f32->fp16; blocks [16384, 24576)
// dequant packed nibbles -> fp16 W. Both memory-bound; one launch.
// ---------------------------------------------------------------------------
#define X_BLOCKS 16384           // 8192*4096/8 elems-per-thread /256
#define W_BLOCKS 8192            // (OUT_F*IN_F/2)/4 bytes-per-thread /256

__global__ void prep_kernel(const float* __restrict__ xf,
                            const int* __restrict__ qw,
                            const int* __restrict__ absmax1,
                            const float* __restrict__ code1,
                            const float* __restrict__ offset1,
                            const float* __restrict__ absmax2,
                            const float* __restrict__ code2) {
    if (blockIdx.x < X_BLOCKS) {
        size_t t = (size_t)blockIdx.x * blockDim.x + threadIdx.x;
        float4 f0 = ((const float4*)xf)[2 * t];
        float4 f1 = ((const float4*)xf)[2 * t + 1];
        __half2 h[4];
        h[0] = __floats2half2_rn(f0.x, f0.y);
        h[1] = __floats2half2_rn(f0.z, f0.w);
        h[2] = __floats2half2_rn(f1.x, f1.y);
        h[3] = __floats2half2_rn(f1.z, f1.w);
        ((int4*)g_X)[t] = *(int4*)h;
    } else {
        int t = (blockIdx.x - X_BLOCKS) * blockDim.x + threadIdx.x;
        int p0 = t * 4;                      // first packed byte index
        int4 q4 = ((const int4*)qw)[t];
        int blk1 = p0 >> 5;                  // 32 packed bytes per primary blk
        int blk2 = p0 >> 7;                  // 128 packed bytes per secondary
        float scale = ((float)absmax1[blk1] / code1[blk1]) *
                      (absmax2[blk2] / code2[blk2]);
        float off = offset1[blk1];
        int b[4] = {q4.x, q4.y, q4.z, q4.w};
        __half2 o[4];
#pragma unroll
        for (int j = 0; j < 4; j++) {
            float lo = (float)(b[j] & 15);
            float hi = (float)((b[j] >> 4) & 15);
            o[j] = __floats2half2_rn((lo - off) * scale, (hi - off) * scale);
        }
        ((int4*)g_W)[t] = *(int4*)o;         // elements [8t, 8t+8)
    }
}

// ---------------------------------------------------------------------------
// GEMM: out[8192,4096](f32, fp16-rounded) = X[M,K](f16) * W[N,K](f16)^T
// mma.sync m16n8k16 f32-accum. BM=128 BN=128 BK=64, 3-stage cp.async.
// 128 threads (4 warps, 2x2 grid, warp tile 64x64), 2 CTAs/SM.
// Cross-boundary fragment pipeline + producer burst hoisted to iteration
// top so LDGSTS issue overlaps slices 0-2 MMAs instead of the boundary.
// ---------------------------------------------------------------------------
#define BM 128
#define BN 128
#define BK 64
#define STAGES 3
#define KITERS (IN_F / BK)                 // 64
#define LDS_ (BK + 8)                      // 72 halves = 144B row stride
#define A_SM (BM * LDS_)                   // halves
#define B_SM (BN * LDS_)
#define STG_SM (A_SM + B_SM)               // 18432 halves per stage
#define GEMM_SMEM (STAGES * STG_SM * 2)    // 110592 bytes per CTA

__device__ __forceinline__ uint32_t smem_u32(const void* p) {
    return (uint32_t)__cvta_generic_to_shared(p);
}
__device__ __forceinline__ void cp_async16(uint32_t s, const void* g) {
    asm volatile("cp.async.cg.shared.global [%0], [%1], 16;\n" :: "r"(s), "l"(g));
}
__device__ __forceinline__ void cp_commit() {
    asm volatile("cp.async.commit_group;\n");
}
template<int N_> __device__ __forceinline__ void cp_wait() {
    asm volatile("cp.async.wait_group %0;\n" :: "n"(N_));
}
__device__ __forceinline__ void ldm_x4(uint32_t& r0, uint32_t& r1,
                                       uint32_t& r2, uint32_t& r3, uint32_t a) {
    asm volatile("ldmatrix.sync.aligned.m8n8.x4.shared.b16 {%0,%1,%2,%3}, [%4];"
                 : "=r"(r0), "=r"(r1), "=r"(r2), "=r"(r3) : "r"(a));
}

__global__ void __launch_bounds__(128, 2)
gemm_kernel(float* __restrict__ O) {
    extern __shared__ __align__(16) __half smem[];

    const int tid  = threadIdx.x;
    const int warp = tid >> 5;
    const int lane = tid & 31;
    const int wm   = warp & 1;    // 2 warps over M: 64 rows each
    const int wn   = warp >> 1;   // 2 warps over N: 64 cols each
    const int bm   = blockIdx.y * BM;
    const int bn   = blockIdx.x * BN;

    // Per stage: A = 1024 16B chunks, B = 1024; 128 threads x 16.
#define LOAD_TILES(stage, kt)                                                  \
    do {                                                                       \
        const int k0 = (kt) * BK;                                              \
        __half* As_ = smem + (size_t)(stage) * STG_SM;                         \
        __half* Bs_ = As_ + A_SM;                                              \
        _Pragma("unroll")                                                      \
        for (int i = 0; i < 8; i++) {                                          \
            int c = tid + i * 128;                                             \
            int r = c >> 3, cc = (c & 7) * 8;                                  \
            cp_async16(smem_u32(As_ + r * LDS_ + cc),                          \
                       g_X + (size_t)(bm + r) * IN_F + k0 + cc);               \
        }                                                                      \
        _Pragma("unroll")                                                      \
        for (int i = 0; i < 8; i++) {                                          \
            int c = tid + i * 128;                                             \
            int r = c >> 3, cc = (c & 7) * 8;                                  \
            cp_async16(smem_u32(Bs_ + r * LDS_ + cc),                          \
                       g_W + (size_t)(bn + r) * IN_F + k0 + cc);               \
        }                                                                      \
    } while (0)

    // Load all fragments for one 16-wide K slice into buffer `buf`.
#define LDM_FRAGS(buf, As_, Bs_, kk)                                           \
    do {                                                                       \
        _Pragma("unroll")                                                      \
        for (int im = 0; im < 4; im++) {                                       \
            int row = wm * 64 + im * 16 + (lane & 15);                         \
            int col = (kk) + (lane >> 4) * 8;                                  \
            ldm_x4(afr[buf][im][0], afr[buf][im][1],                           \
                   afr[buf][im][2], afr[buf][im][3],                           \
                   smem_u32((As_) + row * LDS_ + col));                        \
        }                                                                      \
        _Pragma("unroll")                                                      \
        for (int ib = 0; ib < 4; ib++) {                                       \
            int row = wn * 64 + ib * 16 + (lane & 7) + ((lane >> 4) << 3);     \
            int col = (kk) + ((lane >> 3) & 1) * 8;                            \
            ldm_x4(bfr[buf][ib * 2][0], bfr[buf][ib * 2][1],                   \
                   bfr[buf][ib * 2 + 1][0], bfr[buf][ib * 2 + 1][1],           \
                   smem_u32((Bs_) + row * LDS_ + col));                        \
        }                                                                      \
    } while (0)

#define MMA_SLICE(buf)                                                         \
    do {                                                                       \
        _Pragma("unroll")                                                      \
        for (int im = 0; im < 4; im++)                                         \
            _Pragma("unroll")                                                  \
            for (int in = 0; in < 8; in++) {                                   \
                asm volatile(                                                  \
                    "mma.sync.aligned.m16n8k16.row.col.f32.f16.f16.f32 "       \
                    "{%0,%1,%2,%3},{%4,%5,%6,%7},{%8,%9},{%0,%1,%2,%3};"       \
                    : "+f"(acc[im][in][0]), "+f"(acc[im][in][1]),              \
                      "+f"(acc[im][in][2]), "+f"(acc[im][in][3])               \
                    : "r"(afr[buf][im][0]), "r"(afr[buf][im][1]),              \
                      "r"(afr[buf][im][2]), "r"(afr[buf][im][3]),              \
                      "r"(bfr[buf][in][0]), "r"(bfr[buf][in][1]));             \
            }                                                                  \
    } while (0)

    float acc[4][8][4] = {};
    uint32_t afr[2][4][4];
    uint32_t bfr[2][8][2];

    LOAD_TILES(0, 0); cp_commit();
    LOAD_TILES(1, 1); cp_commit();
    cp_wait<1>();                     // stage 0 resident
    __syncthreads();
    {   // initial slice-0 fragments (iter 0) -> buf0
        const __half* As = smem;
        const __half* Bs = As + A_SM;
        LDM_FRAGS(0, As, Bs, 0);
    }

    for (int kt = 0; kt < KITERS; kt++) {
        const __half* As = smem + (size_t)(kt % STAGES) * STG_SM;
        const __half* Bs = As + A_SM;

        // slice 0 (buf0); hoist next-next stage's producer burst here so its
        // LDGSTS issue cost overlaps slices 0-2 MMA execution. Writes stage
        // (kt-1)%3, whose last reads finished before iter kt-1's boundary
        // sync — all warps are past that by now.
        LDM_FRAGS(1, As, Bs, 16);
        if (kt + 2 < KITERS) LOAD_TILES((kt + 2) % STAGES, kt + 2);
        cp_commit();
        MMA_SLICE(0);

        LDM_FRAGS(0, As, Bs, 32); MMA_SLICE(1);   // slice 1 (buf1)
        LDM_FRAGS(1, As, Bs, 48); MMA_SLICE(0);   // slice 2 (buf0)

        // Boundary: drain G(kt+1) (issued at iter kt-1 -> ~2 iters of lead);
        // G(kt+2) (just issued) stays in flight.
        cp_wait<1>();
        __syncthreads();

        // slice 3: MMAs on pre-loaded buf1; prefetch next iter's slice 0
        // into buf0 from stage kt+1 in parallel (no dependency).
        if (kt + 1 < KITERS) {
            const __half* An = smem + (size_t)((kt + 1) % STAGES) * STG_SM;
            const __half* Bn = An + A_SM;
            LDM_FRAGS(0, An, Bn, 0);
        }
        MMA_SLICE(1);                             // slice 3 (buf1)
    }

    // Epilogue: round through fp16 (reference dequant-matmul is fp16), store f32.
    const int gid  = lane >> 2;
    const int tid4 = lane & 3;
#pragma unroll
    for (int im = 0; im < 4; im++)
#pragma unroll
        for (int in = 0; in < 8; in++) {
            int n = bn + wn * 64 + in * 8 + tid4 * 2;
#pragma unroll
            for (int r = 0; r < 2; r++) {
                int m = bm + wm * 64 + im * 16 + gid + r * 8;
                float2 v;
                v.x = __half2float(__float2half_rn(acc[im][in][r * 2]));
                v.y = __half2float(__float2half_rn(acc[im][in][r * 2 + 1]));
                *(float2*)(O + (size_t)m * OUT_F + n) = v;
            }
        }
#undef LOAD_TILES
#undef LDM_FRAGS
#undef MMA_SLICE
}

// ---------------------------------------------------------------------------
// Inputs (metadata order): x f32, quantized_weight i32, quant_absmax i32,
// quant_code f32, quant_offset f32, state2_absmax f32, state2_code f32.
// Output: float32 [TOKENS, OUT_F].
// ---------------------------------------------------------------------------
extern "C" void kernel_launch(void* const* d_in, const int* in_sizes, int n_in,
                              void* d_out, int out_size) {
    const float* x   = (const float*)d_in[0];
    const int*   qw  = (const int*)d_in[1];
    const int*   am1 = (const int*)d_in[2];
    const float* cd1 = (const float*)d_in[3];
    const float* of1 = (const float*)d_in[4];
    const float* am2 = (const float*)d_in[5];
    const float* cd2 = (const float*)d_in[6];
    float* out = (float*)d_out;

    prep_kernel<<<X_BLOCKS + W_BLOCKS, 256>>>(x, qw, am1, cd1, of1, am2, cd2);

    cudaFuncSetAttribute(gemm_kernel,
                         cudaFuncAttributeMaxDynamicSharedMemorySize, GEMM_SMEM);

    dim3 grid(OUT_F / BN, TOKENS / BM);
    gemm_kernel<<<grid, 128, GEMM_SMEM>>>(out);
}